// round 10
// baseline (speedup 1.0000x reference)
#include <cuda_runtime.h>
#include <cstdint>

#define TC   25
#define HU   64
#define G4   256
#define SPB  64                  // sequences per CTA
#define NTHR 512
#define NSEQ 32768
#define NBLK (NSEQ / SPB)        // 512 CTAs

// dynamic smem layout
#define OFF_UG 0u                // Ug[k][u] float4 = 64*64*16 = 64 KB (ONE copy/SM)
#define HSTRIDE 272u             // 64 seqs*4B = 256, +16 pad (odd 16B-granule stride)
#define HBUF   (64u * HSTRIDE)   // 17408 B
#define OFF_H  65536u            // 2 x h buffer
#define OFF_CH (OFF_H + 2u * HBUF)        // chars [64][25] int = 6400 B
#define SMEM_TOTAL (OFF_CH + 6400u)       // ~106 KB -> 1 CTA/SM, 32 warps

typedef unsigned long long ull;

__device__ float g_EWb[128 * G4];   // EWb[v][j] = (E@W)[v][j] + b[j]

__global__ void ewb_kernel(const float* __restrict__ E,
                           const float* __restrict__ W,
                           const float* __restrict__ b) {
    int v = blockIdx.x, j = threadIdx.x;
    float acc = b[j];
#pragma unroll
    for (int d = 0; d < 32; d++)
        acc = fmaf(E[v * 32 + d], W[d * G4 + j], acc);
    g_EWb[v * G4 + j] = acc;
}

// ---------------- packed f32x2 helpers ----------------
__device__ __forceinline__ ull ffma2(ull a, ull b, ull c) {
    ull d;
    asm("fma.rn.f32x2 %0, %1, %2, %3;" : "=l"(d) : "l"(a), "l"(b), "l"(c));
    return d;
}
__device__ __forceinline__ ull dup2(float x) {
    ull d;
    asm("mov.b64 %0, {%1, %1};" : "=l"(d) : "f"(x));
    return d;
}
__device__ __forceinline__ ull pack2(float x, float y) {
    ull d;
    asm("mov.b64 %0, {%1, %2};" : "=l"(d) : "f"(x), "f"(y));
    return d;
}
__device__ __forceinline__ float2 unpack2(ull v) {
    float2 r;
    asm("mov.b64 {%0, %1}, %2;" : "=f"(r.x), "=f"(r.y) : "l"(v));
    return r;
}
__device__ __forceinline__ float fast_ex2(float x) {
    float y; asm("ex2.approx.f32 %0, %1;" : "=f"(y) : "f"(x)); return y;
}
__device__ __forceinline__ float fast_rcp(float x) {
    float y; asm("rcp.approx.f32 %0, %1;" : "=f"(y) : "f"(x)); return y;
}
__device__ __forceinline__ float sigmoid_(float x) {
    return fast_rcp(1.0f + fast_ex2(-1.4426950408889634f * x));
}
__device__ __forceinline__ float tanh_(float x) {
    return fmaf(-2.0f, fast_rcp(1.0f + fast_ex2(2.8853900817779268f * x)), 1.0f);
}
__device__ __forceinline__ void sts128(uint32_t addr, float x, float y, float z,
                                       float w) {
    asm volatile("st.shared.v4.f32 [%0], {%1,%2,%3,%4};"
                 :: "r"(addr), "f"(x), "f"(y), "f"(z), "f"(w) : "memory");
}
__device__ __forceinline__ uint32_t smem_u32(const void* p) {
    uint32_t a;
    asm("{ .reg .u64 t; cvta.to.shared.u64 t, %1; cvt.u32.u64 %0, t; }"
        : "=r"(a) : "l"(p));
    return a;
}
// group-local barrier: 64 threads of one sequence group
__device__ __forceinline__ void pair_bar(int sgrp) {
    asm volatile("bar.sync %0, 64;" :: "r"(sgrp + 1) : "memory");
}

// ---------------------------------------------------------------------------
__global__ void __launch_bounds__(NTHR, 1)
lstm_kernel(const int* __restrict__ chars,
            const float* __restrict__ U,
            float* __restrict__ out) {
    extern __shared__ __align__(16) char smem[];
    const int tid  = threadIdx.x;
    const int u    = tid & 63;          // hidden unit owned by this thread
    const int sgrp = tid >> 6;          // sequence group (0..7), 8 seqs each
    const int S    = sgrp * 8;

    float4* Ug = (float4*)(smem + OFF_UG);   // Ug[k*64 + u] = {Ui,Uf,Ug,Uo}
    int*    ch = (int*)(smem + OFF_CH);

    // ---- init: rearrange U into gate-interleaved float4s (one shared copy) ----
    for (int e = tid; e < 64 * 64; e += NTHR) {
        int k = e >> 6, uu = e & 63;
        float4 v;
        v.x = U[k * G4 +       uu];
        v.y = U[k * G4 +  64 + uu];
        v.z = U[k * G4 + 128 + uu];
        v.w = U[k * G4 + 192 + uu];
        Ug[e] = v;
    }
    // zero both h buffers (h0 = 0)
    for (uint32_t i = tid * 16; i < 2 * HBUF; i += NTHR * 16)
        *(float4*)(smem + OFF_H + i) = make_float4(0.f, 0.f, 0.f, 0.f);
    // stage chars
    for (int i = tid; i < SPB * TC; i += NTHR)
        ch[i] = chars[blockIdx.x * SPB * TC + i];
    __syncthreads();

    const uint32_t h_base = smem_u32(smem + OFF_H);

    float c_reg[8];
#pragma unroll
    for (int j = 0; j < 8; j++) c_reg[j] = 0.0f;

    for (int step = 0; step < TC; step++) {
        const int rb = step & 1;

        // ---- accumulator init: z = EWb[char] (packed over seq pairs) ----
        ull acc[16];   // acc[g*4 + p] = {z[S+2p][g*64+u], z[S+2p+1][g*64+u]}
        {
            int vv[8];
#pragma unroll
            for (int i = 0; i < 8; i++) vv[i] = ch[(S + i) * TC + step];
#pragma unroll
            for (int p = 0; p < 4; p++) {
                const float* e0 = g_EWb + vv[2 * p]     * G4 + u;
                const float* e1 = g_EWb + vv[2 * p + 1] * G4 + u;
                acc[0  + p] = pack2(e0[0],   e1[0]);
                acc[4  + p] = pack2(e0[64],  e1[64]);
                acc[8  + p] = pack2(e0[128], e1[128]);
                acc[12 + p] = pack2(e0[192], e1[192]);
            }
        }

        // ---- recurrent GEMM: z += h @ U (f32x2, 16 MACs per k) ----
        const char*   hb  = smem + OFF_H + rb * HBUF + sgrp * 32;
        const float4* ugp = Ug + u;
#pragma unroll 8
        for (int k = 0; k < 64; k++) {
            float4 ug = ugp[k * 64];
            ulonglong2 h01 = *(const ulonglong2*)(hb + k * HSTRIDE);
            ulonglong2 h23 = *(const ulonglong2*)(hb + k * HSTRIDE + 16);
            ull d;
            d = dup2(ug.x);
            acc[0]  = ffma2(h01.x, d, acc[0]);  acc[1]  = ffma2(h01.y, d, acc[1]);
            acc[2]  = ffma2(h23.x, d, acc[2]);  acc[3]  = ffma2(h23.y, d, acc[3]);
            d = dup2(ug.y);
            acc[4]  = ffma2(h01.x, d, acc[4]);  acc[5]  = ffma2(h01.y, d, acc[5]);
            acc[6]  = ffma2(h23.x, d, acc[6]);  acc[7]  = ffma2(h23.y, d, acc[7]);
            d = dup2(ug.z);
            acc[8]  = ffma2(h01.x, d, acc[8]);  acc[9]  = ffma2(h01.y, d, acc[9]);
            acc[10] = ffma2(h23.x, d, acc[10]); acc[11] = ffma2(h23.y, d, acc[11]);
            d = dup2(ug.w);
            acc[12] = ffma2(h01.x, d, acc[12]); acc[13] = ffma2(h01.y, d, acc[13]);
            acc[14] = ffma2(h23.x, d, acc[14]); acc[15] = ffma2(h23.y, d, acc[15]);
        }

        // ---- gates in registers ----
        float hv[8];
#pragma unroll
        for (int p = 0; p < 4; p++) {
            float2 zi = unpack2(acc[0  + p]);
            float2 zf = unpack2(acc[4  + p]);
            float2 zg = unpack2(acc[8  + p]);
            float2 zo = unpack2(acc[12 + p]);
            {
                float ig = sigmoid_(zi.x), fg = sigmoid_(zf.x);
                float gg = tanh_(zg.x),    og = sigmoid_(zo.x);
                float c  = fmaf(fg, c_reg[2 * p], ig * gg);
                c_reg[2 * p] = c;
                hv[2 * p] = og * tanh_(c);
            }
            {
                float ig = sigmoid_(zi.y), fg = sigmoid_(zf.y);
                float gg = tanh_(zg.y),    og = sigmoid_(zo.y);
                float c  = fmaf(fg, c_reg[2 * p + 1], ig * gg);
                c_reg[2 * p + 1] = c;
                hv[2 * p + 1] = og * tanh_(c);
            }
        }

        if (step < TC - 1) {
            // write h[u][S..S+7] as two conflict-free STS.128
            uint32_t hw = h_base + (rb ^ 1) * HBUF + u * HSTRIDE + S * 4;
            sts128(hw,      hv[0], hv[1], hv[2], hv[3]);
            sts128(hw + 16, hv[4], hv[5], hv[6], hv[7]);
            pair_bar(sgrp);   // h exchange is group-local (64 threads)
        } else {
            float* orow = out + (size_t)(blockIdx.x * SPB + S) * HU + u;
#pragma unroll
            for (int i = 0; i < 8; i++)
                orow[(size_t)i * HU] = hv[i];
        }
    }
}

extern "C" void kernel_launch(void* const* d_in, const int* in_sizes, int n_in,
                              void* d_out, int out_size) {
    const int*   chars = (const int*)d_in[0];
    const float* E     = (const float*)d_in[1];
    const float* W     = (const float*)d_in[2];
    const float* U     = (const float*)d_in[3];
    const float* b     = (const float*)d_in[4];
    float* out = (float*)d_out;

    cudaFuncSetAttribute(lstm_kernel,
                         cudaFuncAttributeMaxDynamicSharedMemorySize, SMEM_TOTAL);
    ewb_kernel<<<128, 256>>>(E, W, b);
    lstm_kernel<<<NBLK, NTHR, SMEM_TOTAL>>>(chars, U, out);
}

// round 11
// speedup vs baseline: 1.1704x; 1.1704x over previous
#include <cuda_runtime.h>
#include <cstdint>

#define TC   25
#define HU   64
#define G4   256
#define SPB  32                  // sequences per CTA
#define NTHR 256
#define NSEQ 32768
#define NBLK (NSEQ / SPB)        // 1024 CTAs

// dynamic smem layout (R9 proven config)
#define OFF_UG 0u                // Ug[k][u] float4 = 64*64*16 = 64 KB
#define HSTRIDE 144              // bytes per h row (36 floats; STS.128 conflict-free)
#define HBUF   (64u * HSTRIDE)   // 9216 B
#define OFF_H  65536u            // 2 x h buffer
#define OFF_CH (OFF_H + 2u * HBUF)        // chars [32][25] int = 3200 B
#define SMEM_TOTAL (OFF_CH + 3200u)       // ~87 KB -> 2 CTAs/SM

typedef unsigned long long ull;

__device__ float g_EWb[128 * G4];   // EWb[v][j] = (E@W)[v][j] + b[j]

__global__ void ewb_kernel(const float* __restrict__ E,
                           const float* __restrict__ W,
                           const float* __restrict__ b) {
    int v = blockIdx.x, j = threadIdx.x;
    float acc = b[j];
#pragma unroll
    for (int d = 0; d < 32; d++)
        acc = fmaf(E[v * 32 + d], W[d * G4 + j], acc);
    g_EWb[v * G4 + j] = acc;
}

// ---------------- packed f32x2 helpers ----------------
__device__ __forceinline__ ull ffma2(ull a, ull b, ull c) {
    ull d;
    asm("fma.rn.f32x2 %0, %1, %2, %3;" : "=l"(d) : "l"(a), "l"(b), "l"(c));
    return d;
}
__device__ __forceinline__ ull dup2(float x) {
    ull d;
    asm("mov.b64 %0, {%1, %1};" : "=l"(d) : "f"(x));
    return d;
}
__device__ __forceinline__ ull pack2(float x, float y) {
    ull d;
    asm("mov.b64 %0, {%1, %2};" : "=l"(d) : "f"(x), "f"(y));
    return d;
}
__device__ __forceinline__ float2 unpack2(ull v) {
    float2 r;
    asm("mov.b64 {%0, %1}, %2;" : "=f"(r.x), "=f"(r.y) : "l"(v));
    return r;
}
__device__ __forceinline__ float fast_ex2(float x) {
    float y; asm("ex2.approx.f32 %0, %1;" : "=f"(y) : "f"(x)); return y;
}
__device__ __forceinline__ float fast_rcp(float x) {
    float y; asm("rcp.approx.f32 %0, %1;" : "=f"(y) : "f"(x)); return y;
}
__device__ __forceinline__ float sigmoid_(float x) {
    return fast_rcp(1.0f + fast_ex2(-1.4426950408889634f * x));
}
__device__ __forceinline__ float tanh_(float x) {
    return fmaf(-2.0f, fast_rcp(1.0f + fast_ex2(2.8853900817779268f * x)), 1.0f);
}
__device__ __forceinline__ void sts128(uint32_t addr, float x, float y, float z,
                                       float w) {
    asm volatile("st.shared.v4.f32 [%0], {%1,%2,%3,%4};"
                 :: "r"(addr), "f"(x), "f"(y), "f"(z), "f"(w) : "memory");
}
__device__ __forceinline__ uint32_t smem_u32(const void* p) {
    uint32_t a;
    asm("{ .reg .u64 t; cvta.to.shared.u64 t, %1; cvt.u32.u64 %0, t; }"
        : "=r"(a) : "l"(p));
    return a;
}
__device__ __forceinline__ void pair_bar(int sgrp) {
    asm volatile("bar.sync %0, 64;" :: "r"(sgrp + 1) : "memory");
}

// ---------------------------------------------------------------------------
__global__ void __launch_bounds__(NTHR, 2)
lstm_kernel(const int* __restrict__ chars,
            const float* __restrict__ U,
            float* __restrict__ out) {
    extern __shared__ __align__(16) char smem[];
    const int tid  = threadIdx.x;
    const int u    = tid & 63;          // hidden unit owned by this thread
    const int sgrp = tid >> 6;          // sequence group (0..3), 8 seqs each
    const int S    = sgrp * 8;

    float4* Ug = (float4*)(smem + OFF_UG);   // Ug[k*64 + u] = {Ui,Uf,Ug,Uo}
    int*    ch = (int*)(smem + OFF_CH);

    // ---- init: rearrange U into gate-interleaved float4s ----
    for (int e = tid; e < 64 * 64; e += NTHR) {
        int k = e >> 6, uu = e & 63;
        float4 v;
        v.x = __ldg(&U[k * G4 +       uu]);
        v.y = __ldg(&U[k * G4 +  64 + uu]);
        v.z = __ldg(&U[k * G4 + 128 + uu]);
        v.w = __ldg(&U[k * G4 + 192 + uu]);
        Ug[e] = v;
    }
    // zero both h buffers (h0 = 0)
    for (uint32_t i = tid * 16; i < 2 * HBUF; i += NTHR * 16)
        *(float4*)(smem + OFF_H + i) = make_float4(0.f, 0.f, 0.f, 0.f);
    // stage chars
    for (int i = tid; i < SPB * TC; i += NTHR)
        ch[i] = chars[blockIdx.x * SPB * TC + i];
    __syncthreads();

    const uint32_t h_base = smem_u32(smem + OFF_H);

    float c_reg[8];
#pragma unroll
    for (int j = 0; j < 8; j++) c_reg[j] = 0.0f;

    // ---- prefetch EWb rows for step 0 ----
    // pf0[p*4+g] = EWb[ch[S+2p]][g*64+u], pf1 likewise for seq S+2p+1
    float pf0[16], pf1[16];
    {
#pragma unroll
        for (int p = 0; p < 4; p++) {
            const float* e0 = g_EWb + ch[(S + 2 * p)     * TC] * G4 + u;
            const float* e1 = g_EWb + ch[(S + 2 * p + 1) * TC] * G4 + u;
#pragma unroll
            for (int g = 0; g < 4; g++) {
                pf0[p * 4 + g] = __ldg(e0 + g * 64);
                pf1[p * 4 + g] = __ldg(e1 + g * 64);
            }
        }
    }

#pragma unroll 1
    for (int step = 0; step < TC; step++) {
        const int rb = step & 1;

        // ---- accumulator init from prefetched EWb ----
        ull acc[16];   // acc[g*4 + p] = {z[S+2p][g*64+u], z[S+2p+1][g*64+u]}
#pragma unroll
        for (int p = 0; p < 4; p++)
#pragma unroll
            for (int g = 0; g < 4; g++)
                acc[g * 4 + p] = pack2(pf0[p * 4 + g], pf1[p * 4 + g]);

        // ---- issue next step's EWb prefetch; GEMM below hides the latency ----
        if (step + 1 < TC) {
#pragma unroll
            for (int p = 0; p < 4; p++) {
                const float* e0 = g_EWb + ch[(S + 2 * p)     * TC + step + 1] * G4 + u;
                const float* e1 = g_EWb + ch[(S + 2 * p + 1) * TC + step + 1] * G4 + u;
#pragma unroll
                for (int g = 0; g < 4; g++) {
                    pf0[p * 4 + g] = __ldg(e0 + g * 64);
                    pf1[p * 4 + g] = __ldg(e1 + g * 64);
                }
            }
        }

        // ---- recurrent GEMM: z += h @ U (f32x2, 16 MACs per k) ----
        const char*   hb  = smem + OFF_H + rb * HBUF + sgrp * 32;
        const float4* ugp = Ug + u;
#pragma unroll 8
        for (int k = 0; k < 64; k++) {
            float4 ug = ugp[k * 64];
            ulonglong2 h01 = *(const ulonglong2*)(hb + k * HSTRIDE);
            ulonglong2 h23 = *(const ulonglong2*)(hb + k * HSTRIDE + 16);
            ull d;
            d = dup2(ug.x);
            acc[0]  = ffma2(h01.x, d, acc[0]);  acc[1]  = ffma2(h01.y, d, acc[1]);
            acc[2]  = ffma2(h23.x, d, acc[2]);  acc[3]  = ffma2(h23.y, d, acc[3]);
            d = dup2(ug.y);
            acc[4]  = ffma2(h01.x, d, acc[4]);  acc[5]  = ffma2(h01.y, d, acc[5]);
            acc[6]  = ffma2(h23.x, d, acc[6]);  acc[7]  = ffma2(h23.y, d, acc[7]);
            d = dup2(ug.z);
            acc[8]  = ffma2(h01.x, d, acc[8]);  acc[9]  = ffma2(h01.y, d, acc[9]);
            acc[10] = ffma2(h23.x, d, acc[10]); acc[11] = ffma2(h23.y, d, acc[11]);
            d = dup2(ug.w);
            acc[12] = ffma2(h01.x, d, acc[12]); acc[13] = ffma2(h01.y, d, acc[13]);
            acc[14] = ffma2(h23.x, d, acc[14]); acc[15] = ffma2(h23.y, d, acc[15]);
        }

        // ---- gates in registers ----
        float hv[8];
#pragma unroll
        for (int p = 0; p < 4; p++) {
            float2 zi = unpack2(acc[0  + p]);
            float2 zf = unpack2(acc[4  + p]);
            float2 zg = unpack2(acc[8  + p]);
            float2 zo = unpack2(acc[12 + p]);
            {
                float ig = sigmoid_(zi.x), fg = sigmoid_(zf.x);
                float gg = tanh_(zg.x),    og = sigmoid_(zo.x);
                float c  = fmaf(fg, c_reg[2 * p], ig * gg);
                c_reg[2 * p] = c;
                hv[2 * p] = og * tanh_(c);
            }
            {
                float ig = sigmoid_(zi.y), fg = sigmoid_(zf.y);
                float gg = tanh_(zg.y),    og = sigmoid_(zo.y);
                float c  = fmaf(fg, c_reg[2 * p + 1], ig * gg);
                c_reg[2 * p + 1] = c;
                hv[2 * p + 1] = og * tanh_(c);
            }
        }

        if (step < TC - 1) {
            // write h[u][S..S+7] as two conflict-free STS.128
            uint32_t hw = h_base + (rb ^ 1) * HBUF + u * HSTRIDE + S * 4;
            sts128(hw,      hv[0], hv[1], hv[2], hv[3]);
            sts128(hw + 16, hv[4], hv[5], hv[6], hv[7]);
            pair_bar(sgrp);   // h exchange is group-local (64 threads)
        } else {
            float* orow = out + (size_t)(blockIdx.x * SPB + S) * HU + u;
#pragma unroll
            for (int i = 0; i < 8; i++)
                orow[(size_t)i * HU] = hv[i];
        }
    }
}

extern "C" void kernel_launch(void* const* d_in, const int* in_sizes, int n_in,
                              void* d_out, int out_size) {
    const int*   chars = (const int*)d_in[0];
    const float* E     = (const float*)d_in[1];
    const float* W     = (const float*)d_in[2];
    const float* U     = (const float*)d_in[3];
    const float* b     = (const float*)d_in[4];
    float* out = (float*)d_out;

    cudaFuncSetAttribute(lstm_kernel,
                         cudaFuncAttributeMaxDynamicSharedMemorySize, SMEM_TOTAL);
    ewb_kernel<<<128, 256>>>(E, W, b);
    lstm_kernel<<<NBLK, NTHR, SMEM_TOTAL>>>(chars, U, out);
}

// round 12
// speedup vs baseline: 1.3418x; 1.1465x over previous
#include <cuda_runtime.h>
#include <cstdint>

#define TC   25
#define HU   64
#define G4   256
#define SPB  32                  // sequences per CTA
#define NTHR 256
#define NSEQ 32768
#define NBLK (NSEQ / SPB)        // 1024 CTAs

// dynamic smem layout (R9/R11 proven config)
#define OFF_UG 0u                // Ug[k][u] float4 = 64*64*16 = 64 KB
#define HSTRIDE 144              // bytes per h row (36 floats; STS.128 conflict-free)
#define HBUF   (64u * HSTRIDE)   // 9216 B
#define OFF_H  65536u            // 2 x h buffer
#define OFF_CH (OFF_H + 2u * HBUF)        // chars [32][25] int = 3200 B
#define SMEM_TOTAL (OFF_CH + 3200u)       // ~87 KB -> 2 CTAs/SM

typedef unsigned long long ull;

__device__ float g_EWb[128 * G4];   // EWb[v][j] = (E@W)[v][j] + b[j]

__global__ void ewb_kernel(const float* __restrict__ E,
                           const float* __restrict__ W,
                           const float* __restrict__ b) {
    int v = blockIdx.x, j = threadIdx.x;
    float acc = b[j];
#pragma unroll
    for (int d = 0; d < 32; d++)
        acc = fmaf(E[v * 32 + d], W[d * G4 + j], acc);
    g_EWb[v * G4 + j] = acc;
}

// ---------------- packed f32x2 helpers ----------------
__device__ __forceinline__ ull ffma2(ull a, ull b, ull c) {
    ull d;
    asm("fma.rn.f32x2 %0, %1, %2, %3;" : "=l"(d) : "l"(a), "l"(b), "l"(c));
    return d;
}
__device__ __forceinline__ ull dup2(float x) {
    ull d;
    asm("mov.b64 %0, {%1, %1};" : "=l"(d) : "f"(x));
    return d;
}
__device__ __forceinline__ ull pack2(float x, float y) {
    ull d;
    asm("mov.b64 %0, {%1, %2};" : "=l"(d) : "f"(x), "f"(y));
    return d;
}
__device__ __forceinline__ float2 unpack2(ull v) {
    float2 r;
    asm("mov.b64 {%0, %1}, %2;" : "=f"(r.x), "=f"(r.y) : "l"(v));
    return r;
}
// single-MUFU tanh (sm_75+). abs err ~1e-4.
__device__ __forceinline__ float tanha(float x) {
    float y; asm("tanh.approx.f32 %0, %1;" : "=f"(y) : "f"(x)); return y;
}
// sigmoid(x) = 0.5 + 0.5*tanh(x/2): 1 MUFU + 2 fma
__device__ __forceinline__ float sigmoid_(float x) {
    return fmaf(0.5f, tanha(0.5f * x), 0.5f);
}
__device__ __forceinline__ float tanh_(float x) {
    return tanha(x);
}
__device__ __forceinline__ void sts128(uint32_t addr, float x, float y, float z,
                                       float w) {
    asm volatile("st.shared.v4.f32 [%0], {%1,%2,%3,%4};"
                 :: "r"(addr), "f"(x), "f"(y), "f"(z), "f"(w) : "memory");
}
__device__ __forceinline__ uint32_t smem_u32(const void* p) {
    uint32_t a;
    asm("{ .reg .u64 t; cvta.to.shared.u64 t, %1; cvt.u32.u64 %0, t; }"
        : "=r"(a) : "l"(p));
    return a;
}
__device__ __forceinline__ void pair_bar(int sgrp) {
    asm volatile("bar.sync %0, 64;" :: "r"(sgrp + 1) : "memory");
}

// ---------------------------------------------------------------------------
__global__ void __launch_bounds__(NTHR, 2)
lstm_kernel(const int* __restrict__ chars,
            const float* __restrict__ U,
            float* __restrict__ out) {
    extern __shared__ __align__(16) char smem[];
    const int tid  = threadIdx.x;
    const int u    = tid & 63;          // hidden unit owned by this thread
    const int sgrp = tid >> 6;          // sequence group (0..3), 8 seqs each
    const int S    = sgrp * 8;

    float4* Ug = (float4*)(smem + OFF_UG);   // Ug[k*64 + u] = {Ui,Uf,Ug,Uo}
    int*    ch = (int*)(smem + OFF_CH);

    // ---- init: rearrange U into gate-interleaved float4s ----
    for (int e = tid; e < 64 * 64; e += NTHR) {
        int k = e >> 6, uu = e & 63;
        float4 v;
        v.x = __ldg(&U[k * G4 +       uu]);
        v.y = __ldg(&U[k * G4 +  64 + uu]);
        v.z = __ldg(&U[k * G4 + 128 + uu]);
        v.w = __ldg(&U[k * G4 + 192 + uu]);
        Ug[e] = v;
    }
    // zero both h buffers (h0 = 0)
    for (uint32_t i = tid * 16; i < 2 * HBUF; i += NTHR * 16)
        *(float4*)(smem + OFF_H + i) = make_float4(0.f, 0.f, 0.f, 0.f);
    // stage chars
    for (int i = tid; i < SPB * TC; i += NTHR)
        ch[i] = chars[blockIdx.x * SPB * TC + i];
    __syncthreads();

    const uint32_t h_base = smem_u32(smem + OFF_H);

    float c_reg[8];
#pragma unroll
    for (int j = 0; j < 8; j++) c_reg[j] = 0.0f;

    // ---- prefetch EWb rows for step 0 ----
    float pf0[16], pf1[16];
    {
#pragma unroll
        for (int p = 0; p < 4; p++) {
            const float* e0 = g_EWb + ch[(S + 2 * p)     * TC] * G4 + u;
            const float* e1 = g_EWb + ch[(S + 2 * p + 1) * TC] * G4 + u;
#pragma unroll
            for (int g = 0; g < 4; g++) {
                pf0[p * 4 + g] = __ldg(e0 + g * 64);
                pf1[p * 4 + g] = __ldg(e1 + g * 64);
            }
        }
    }

#pragma unroll 1
    for (int step = 0; step < TC; step++) {
        const int rb = step & 1;

        // ---- accumulator init from prefetched EWb ----
        ull acc[16];   // acc[g*4 + p] = {z[S+2p][g*64+u], z[S+2p+1][g*64+u]}
#pragma unroll
        for (int p = 0; p < 4; p++)
#pragma unroll
            for (int g = 0; g < 4; g++)
                acc[g * 4 + p] = pack2(pf0[p * 4 + g], pf1[p * 4 + g]);

        // ---- issue next step's EWb prefetch; GEMM below hides the latency ----
        if (step + 1 < TC) {
#pragma unroll
            for (int p = 0; p < 4; p++) {
                const float* e0 = g_EWb + ch[(S + 2 * p)     * TC + step + 1] * G4 + u;
                const float* e1 = g_EWb + ch[(S + 2 * p + 1) * TC + step + 1] * G4 + u;
#pragma unroll
                for (int g = 0; g < 4; g++) {
                    pf0[p * 4 + g] = __ldg(e0 + g * 64);
                    pf1[p * 4 + g] = __ldg(e1 + g * 64);
                }
            }
        }

        // ---- recurrent GEMM: z += h @ U (f32x2, 16 MACs per k) ----
        const char*   hb  = smem + OFF_H + rb * HBUF + sgrp * 32;
        const float4* ugp = Ug + u;
#pragma unroll 8
        for (int k = 0; k < 64; k++) {
            float4 ug = ugp[k * 64];
            ulonglong2 h01 = *(const ulonglong2*)(hb + k * HSTRIDE);
            ulonglong2 h23 = *(const ulonglong2*)(hb + k * HSTRIDE + 16);
            ull d;
            d = dup2(ug.x);
            acc[0]  = ffma2(h01.x, d, acc[0]);  acc[1]  = ffma2(h01.y, d, acc[1]);
            acc[2]  = ffma2(h23.x, d, acc[2]);  acc[3]  = ffma2(h23.y, d, acc[3]);
            d = dup2(ug.y);
            acc[4]  = ffma2(h01.x, d, acc[4]);  acc[5]  = ffma2(h01.y, d, acc[5]);
            acc[6]  = ffma2(h23.x, d, acc[6]);  acc[7]  = ffma2(h23.y, d, acc[7]);
            d = dup2(ug.z);
            acc[8]  = ffma2(h01.x, d, acc[8]);  acc[9]  = ffma2(h01.y, d, acc[9]);
            acc[10] = ffma2(h23.x, d, acc[10]); acc[11] = ffma2(h23.y, d, acc[11]);
            d = dup2(ug.w);
            acc[12] = ffma2(h01.x, d, acc[12]); acc[13] = ffma2(h01.y, d, acc[13]);
            acc[14] = ffma2(h23.x, d, acc[14]); acc[15] = ffma2(h23.y, d, acc[15]);
        }

        // ---- gates in registers (5 MUFU per hidden unit) ----
        float hv[8];
#pragma unroll
        for (int p = 0; p < 4; p++) {
            float2 zi = unpack2(acc[0  + p]);
            float2 zf = unpack2(acc[4  + p]);
            float2 zg = unpack2(acc[8  + p]);
            float2 zo = unpack2(acc[12 + p]);
            {
                float ig = sigmoid_(zi.x), fg = sigmoid_(zf.x);
                float gg = tanh_(zg.x),    og = sigmoid_(zo.x);
                float c  = fmaf(fg, c_reg[2 * p], ig * gg);
                c_reg[2 * p] = c;
                hv[2 * p] = og * tanh_(c);
            }
            {
                float ig = sigmoid_(zi.y), fg = sigmoid_(zf.y);
                float gg = tanh_(zg.y),    og = sigmoid_(zo.y);
                float c  = fmaf(fg, c_reg[2 * p + 1], ig * gg);
                c_reg[2 * p + 1] = c;
                hv[2 * p + 1] = og * tanh_(c);
            }
        }

        if (step < TC - 1) {
            uint32_t hw = h_base + (rb ^ 1) * HBUF + u * HSTRIDE + S * 4;
            sts128(hw,      hv[0], hv[1], hv[2], hv[3]);
            sts128(hw + 16, hv[4], hv[5], hv[6], hv[7]);
            pair_bar(sgrp);   // h exchange is group-local (64 threads)
        } else {
            float* orow = out + (size_t)(blockIdx.x * SPB + S) * HU + u;
#pragma unroll
            for (int i = 0; i < 8; i++)
                orow[(size_t)i * HU] = hv[i];
        }
    }
}

extern "C" void kernel_launch(void* const* d_in, const int* in_sizes, int n_in,
                              void* d_out, int out_size) {
    const int*   chars = (const int*)d_in[0];
    const float* E     = (const float*)d_in[1];
    const float* W     = (const float*)d_in[2];
    const float* U     = (const float*)d_in[3];
    const float* b     = (const float*)d_in[4];
    float* out = (float*)d_out;

    cudaFuncSetAttribute(lstm_kernel,
                         cudaFuncAttributeMaxDynamicSharedMemorySize, SMEM_TOTAL);
    ewb_kernel<<<128, 256>>>(E, W, b);
    lstm_kernel<<<NBLK, NTHR, SMEM_TOTAL>>>(chars, U, out);
}

// round 13
// speedup vs baseline: 2.2915x; 1.7077x over previous
#include <cuda_runtime.h>
#include <cstdint>

#define TC   25
#define HU   64
#define G4   256
#define SPB  32                  // sequences per CTA
#define NTHR 256
#define NSEQ 32768
#define NBLK (NSEQ / SPB)        // 1024 CTAs

// smem layout
#define OFF_U  0u                // U in B-fragment order: 4w*4g*2up*8kt*32lane*8B = 64 KB
#define OFF_H  65536u            // 2 bufs x [2 mtiles][8 kt][32 lanes][4 slots] f32 = 16 KB
#define HBUF   8192u
#define OFF_CH (OFF_H + 2u * HBUF)        // chars [32][25] int = 3200 B
#define SMEM_TOTAL (OFF_CH + 3200u)       // ~85 KB -> 2 CTAs/SM

__device__ float g_EWb[128 * G4];   // EWb[v][j] = (E@W)[v][j] + b[j]  (exact fp32)

__global__ void ewb_kernel(const float* __restrict__ E,
                           const float* __restrict__ W,
                           const float* __restrict__ b) {
    int v = blockIdx.x, j = threadIdx.x;
    float acc = b[j];
#pragma unroll
    for (int d = 0; d < 32; d++)
        acc = fmaf(E[v * 32 + d], W[d * G4 + j], acc);
    g_EWb[v * G4 + j] = acc;
}

// ---------------- helpers ----------------
__device__ __forceinline__ uint32_t smem_u32(const void* p) {
    uint32_t a;
    asm("{ .reg .u64 t; cvta.to.shared.u64 t, %1; cvt.u32.u64 %0, t; }"
        : "=r"(a) : "l"(p));
    return a;
}
__device__ __forceinline__ float tanha(float x) {
    float y; asm("tanh.approx.f32 %0, %1;" : "=f"(y) : "f"(x)); return y;
}
__device__ __forceinline__ float sigmoid_(float x) {
    return fmaf(0.5f, tanha(0.5f * x), 0.5f);
}
__device__ __forceinline__ uint32_t tf32_(float x) {
    uint32_t u; asm("cvt.rna.tf32.f32 %0, %1;" : "=r"(u) : "f"(x)); return u;
}
__device__ __forceinline__ void lds128u(uint4& v, uint32_t a) {
    asm volatile("ld.shared.v4.b32 {%0,%1,%2,%3}, [%4];"
                 : "=r"(v.x), "=r"(v.y), "=r"(v.z), "=r"(v.w) : "r"(a));
}
__device__ __forceinline__ void lds64u(uint2& v, uint32_t a) {
    asm volatile("ld.shared.v2.b32 {%0,%1}, [%2];"
                 : "=r"(v.x), "=r"(v.y) : "r"(a));
}
__device__ __forceinline__ void sts32(uint32_t a, uint32_t v) {
    asm volatile("st.shared.b32 [%0], %1;" :: "r"(a), "r"(v) : "memory");
}
__device__ __forceinline__ void sts128z(uint32_t a) {
    asm volatile("st.shared.v4.b32 [%0], {%1,%1,%1,%1};" :: "r"(a), "r"(0u) : "memory");
}
// m16n8k8 tf32 MMA, D==C in-place accumulate
__device__ __forceinline__ void mma8(float& d0, float& d1, float& d2, float& d3,
                                     const uint4& a, const uint2& b) {
    asm volatile(
        "mma.sync.aligned.m16n8k8.row.col.f32.tf32.tf32.f32 "
        "{%0,%1,%2,%3}, {%4,%5,%6,%7}, {%8,%9}, {%0,%1,%2,%3};"
        : "+f"(d0), "+f"(d1), "+f"(d2), "+f"(d3)
        : "r"(a.x), "r"(a.y), "r"(a.z), "r"(a.w), "r"(b.x), "r"(b.y));
}
__device__ __forceinline__ void group_bar(int m) {
    asm volatile("bar.sync %0, 128;" :: "r"(m + 1) : "memory");
}

// ---------------------------------------------------------------------------
__global__ void __launch_bounds__(NTHR, 2)
lstm_kernel(const int* __restrict__ chars,
            const float* __restrict__ U,
            float* __restrict__ out) {
    extern __shared__ __align__(16) char smem[];
    const uint32_t sb = smem_u32(smem);
    const int tid   = threadIdx.x;
    const int lane  = tid & 31;
    const int wid   = tid >> 5;
    const int m     = wid >> 2;          // m-tile (16 seqs) : 0 or 1
    const int w     = wid & 3;           // unit group (16 units)
    const int r     = lane >> 2;         // D rows r, r+8 within m-tile
    const int cpair = lane & 3;          // D cols 2*cpair, 2*cpair+1 within n-tile

    int* ch = (int*)(smem + OFF_CH);

    // ---- stage U into B-fragment order (tf32 rounded) ----
    // value U[k][n] -> tile (w=uu/16, g, up=(uu%16)/8, kt=k/8), lane = ncol*4+(krow&3), slot = krow>>2
    for (int idx = tid; idx < 64 * 256; idx += NTHR) {
        int n = idx & 255, k = idx >> 8;
        int g = n >> 6, uu = n & 63;
        int ww = uu >> 4, up = (uu >> 3) & 1, ncol = uu & 7;
        int kt = k >> 3, krow = k & 7;
        uint32_t L = ncol * 4 + (krow & 3);
        uint32_t addr = sb + OFF_U +
            (((((ww * 4 + g) * 2 + up) * 8 + kt) * 32 + L) * 8) + (krow >> 2) * 4;
        sts32(addr, tf32_(U[k * G4 + n]));
    }
    // zero both h buffers (h0 = 0)
    for (uint32_t i = tid * 16; i < 2 * HBUF; i += NTHR * 16)
        sts128z(sb + OFF_H + i);
    // stage chars
    for (int i = tid; i < SPB * TC; i += NTHR)
        ch[i] = chars[blockIdx.x * SPB * TC + i];
    __syncthreads();

    const int lseq = m * 16 + r;               // local seq of D row r
    const int ucol = w * 16 + 2 * cpair;       // unit base col (+up*8, +e)

    float c_reg[8];                            // [up*4 + el]
#pragma unroll
    for (int j = 0; j < 8; j++) c_reg[j] = 0.0f;

    // ---- D init: prefetch EWb rows for step 0 directly into D (= mma C) ----
    float d[32];                               // d[g*8 + up*4 + el]
    {
        int v0 = ch[lseq * TC], v1 = ch[(lseq + 8) * TC];
#pragma unroll
        for (int g = 0; g < 4; g++)
#pragma unroll
            for (int up = 0; up < 2; up++) {
                float2 t0 = __ldg((const float2*)(g_EWb + v0 * G4 + g * 64 + ucol + up * 8));
                float2 t1 = __ldg((const float2*)(g_EWb + v1 * G4 + g * 64 + ucol + up * 8));
                d[g * 8 + up * 4 + 0] = t0.x; d[g * 8 + up * 4 + 1] = t0.y;
                d[g * 8 + up * 4 + 2] = t1.x; d[g * 8 + up * 4 + 3] = t1.y;
            }
    }

#pragma unroll 1
    for (int step = 0; step < TC; step++) {
        const int rb = step & 1;

        group_bar(m);   // h_sm[rb] complete for this m-tile

        // ---- GEMM: D += A(h) * B(U), 64 HMMA ----
        const uint32_t ha = sb + OFF_H + rb * HBUF + m * 4096 + lane * 16;
        const uint32_t ub = sb + OFF_U + (uint32_t)w * 4 * 2 * 8 * 32 * 8 + lane * 8;
#pragma unroll
        for (int kt = 0; kt < 8; kt++) {
            uint4 A; lds128u(A, ha + kt * 512);
#pragma unroll
            for (int g = 0; g < 4; g++)
#pragma unroll
                for (int up = 0; up < 2; up++) {
                    uint2 B;
                    lds64u(B, ub + (((g * 2 + up) * 8 + kt) * 32) * 8);
                    mma8(d[g * 8 + up * 4 + 0], d[g * 8 + up * 4 + 1],
                         d[g * 8 + up * 4 + 2], d[g * 8 + up * 4 + 3], A, B);
                }
        }

        // ---- gates (thread-local: all 4 gates of each (seq,unit) pair) ----
        float hv[8];   // [up*4 + el], el = hh*2 + e
#pragma unroll
        for (int up = 0; up < 2; up++)
#pragma unroll
            for (int el = 0; el < 4; el++) {
                float zi = d[ 0 + up * 4 + el];
                float zf = d[ 8 + up * 4 + el];
                float zg = d[16 + up * 4 + el];
                float zo = d[24 + up * 4 + el];
                float ig = sigmoid_(zi), fg = sigmoid_(zf);
                float gg = tanha(zg),    og = sigmoid_(zo);
                float c  = fmaf(fg, c_reg[up * 4 + el], ig * gg);
                c_reg[up * 4 + el] = c;
                hv[up * 4 + el] = og * tanha(c);
            }

        if (step < TC - 1) {
            // ---- write h into A-fragment layout of buffer rb^1 ----
            const uint32_t bw = sb + OFF_H + (rb ^ 1) * HBUF + m * 4096;
#pragma unroll
            for (int up = 0; up < 2; up++)
#pragma unroll
                for (int el = 0; el < 4; el++) {
                    int e = el & 1, hh = el >> 1;
                    int kcol = 2 * cpair + e;                    // 0..7
                    uint32_t addr = bw + (uint32_t)(w * 2 + up) * 512 +
                                    (uint32_t)(r * 4 + (kcol & 3)) * 16 +
                                    (uint32_t)((kcol >> 2) * 2 + hh) * 4;
                    sts32(addr, tf32_(hv[up * 4 + el]));
                }
            // ---- prefetch next step's EWb into D (hidden under next GEMM) ----
            int v0 = ch[lseq * TC + step + 1], v1 = ch[(lseq + 8) * TC + step + 1];
#pragma unroll
            for (int g = 0; g < 4; g++)
#pragma unroll
                for (int up = 0; up < 2; up++) {
                    float2 t0 = __ldg((const float2*)(g_EWb + v0 * G4 + g * 64 + ucol + up * 8));
                    float2 t1 = __ldg((const float2*)(g_EWb + v1 * G4 + g * 64 + ucol + up * 8));
                    d[g * 8 + up * 4 + 0] = t0.x; d[g * 8 + up * 4 + 1] = t0.y;
                    d[g * 8 + up * 4 + 2] = t1.x; d[g * 8 + up * 4 + 3] = t1.y;
                }
        } else {
            // ---- final h -> gmem ----
            const int gs = blockIdx.x * SPB + lseq;
#pragma unroll
            for (int up = 0; up < 2; up++)
#pragma unroll
                for (int hh = 0; hh < 2; hh++) {
                    float2 v = make_float2(hv[up * 4 + hh * 2], hv[up * 4 + hh * 2 + 1]);
                    *(float2*)(out + (size_t)(gs + hh * 8) * HU + ucol + up * 8) = v;
                }
        }
    }
}

extern "C" void kernel_launch(void* const* d_in, const int* in_sizes, int n_in,
                              void* d_out, int out_size) {
    const int*   chars = (const int*)d_in[0];
    const float* E     = (const float*)d_in[1];
    const float* W     = (const float*)d_in[2];
    const float* U     = (const float*)d_in[3];
    const float* b     = (const float*)d_in[4];
    float* out = (float*)d_out;

    cudaFuncSetAttribute(lstm_kernel,
                         cudaFuncAttributeMaxDynamicSharedMemorySize, SMEM_TOTAL);
    ewb_kernel<<<128, 256>>>(E, W, b);
    lstm_kernel<<<NBLK, NTHR, SMEM_TOTAL>>>(chars, U, out);
}

// round 15
// speedup vs baseline: 2.9938x; 1.3065x over previous
#include <cuda_runtime.h>
#include <cstdint>

#define TC   25
#define HU   64
#define G4   256
#define SPB  16                  // sequences per CTA (one m16 tile)
#define NTHR 256
#define NSEQ 32768
#define NBLK (NSEQ / SPB)        // 2048 CTAs

__device__ float g_EWb[128 * G4];   // EWb[v][j] = (E@W)[v][j] + b[j]  (exact fp32)

__global__ void ewb_kernel(const float* __restrict__ E,
                           const float* __restrict__ W,
                           const float* __restrict__ b) {
    int v = blockIdx.x, j = threadIdx.x;
    float acc = b[j];
#pragma unroll
    for (int d = 0; d < 32; d++)
        acc = fmaf(E[v * 32 + d], W[d * G4 + j], acc);
    g_EWb[v * G4 + j] = acc;
}

// ---------------- helpers ----------------
__device__ __forceinline__ uint32_t smem_u32(const void* p) {
    uint32_t a;
    asm("{ .reg .u64 t; cvta.to.shared.u64 t, %1; cvt.u32.u64 %0, t; }"
        : "=r"(a) : "l"(p));
    return a;
}
__device__ __forceinline__ float tanha(float x) {
    float y; asm("tanh.approx.f32 %0, %1;" : "=f"(y) : "f"(x)); return y;
}
__device__ __forceinline__ float sigmoid_(float x) {
    return fmaf(0.5f, tanha(0.5f * x), 0.5f);
}
__device__ __forceinline__ uint32_t tf32_(float x) {
    uint32_t u; asm("cvt.rna.tf32.f32 %0, %1;" : "=r"(u) : "f"(x)); return u;
}
__device__ __forceinline__ void lds128u(uint4& v, uint32_t a) {
    asm volatile("ld.shared.v4.b32 {%0,%1,%2,%3}, [%4];"
                 : "=r"(v.x), "=r"(v.y), "=r"(v.z), "=r"(v.w) : "r"(a));
}
__device__ __forceinline__ void sts32(uint32_t a, uint32_t v) {
    asm volatile("st.shared.b32 [%0], %1;" :: "r"(a), "r"(v) : "memory");
}
// m16n8k8 tf32 MMA, D==C in-place accumulate
__device__ __forceinline__ void mma8(float& d0, float& d1, float& d2, float& d3,
                                     const uint4& a, uint32_t b0, uint32_t b1) {
    asm volatile(
        "mma.sync.aligned.m16n8k8.row.col.f32.tf32.tf32.f32 "
        "{%0,%1,%2,%3}, {%4,%5,%6,%7}, {%8,%9}, {%0,%1,%2,%3};"
        : "+f"(d0), "+f"(d1), "+f"(d2), "+f"(d3)
        : "r"(a.x), "r"(a.y), "r"(a.z), "r"(a.w), "r"(b0), "r"(b1));
}

// ---------------------------------------------------------------------------
// smem: h double buffer in A-fragment layout [buf][kt(8)][lane(32)][slot(4)] f32
//       + chars [16][25]
__global__ void __launch_bounds__(NTHR, 2)
lstm_kernel(const int* __restrict__ chars,
            const float* __restrict__ U,
            float* __restrict__ out) {
    __shared__ __align__(16) float h_sm[2][8 * 32 * 4];   // 2 x 4 KB
    __shared__ int ch[SPB * TC];

    const int tid   = threadIdx.x;
    const int lane  = tid & 31;
    const int w     = tid >> 5;          // warp = unit group: units [8w, 8w+8)
    const int r     = lane >> 2;         // D rows r, r+8
    const int cpair = lane & 3;          // D col pair 2*cpair, 2*cpair+1
    const int klo   = lane & 3;          // B frag k-row low
    const int ncol  = lane >> 2;         // B frag n-col (unit offset 0..7)

    // ---- load B (= U, tf32) fragments into registers: constant all steps ----
    uint32_t breg[4][8][2];
#pragma unroll
    for (int g = 0; g < 4; g++)
#pragma unroll
        for (int kt = 0; kt < 8; kt++) {
            int col = g * 64 + 8 * w + ncol;
            breg[g][kt][0] = tf32_(__ldg(&U[(kt * 8 + klo)     * G4 + col]));
            breg[g][kt][1] = tf32_(__ldg(&U[(kt * 8 + klo + 4) * G4 + col]));
        }

    // zero h buffer 0 (h0 = 0)
    for (int i = tid; i < 8 * 32 * 4; i += NTHR) h_sm[0][i] = 0.0f;
    // stage chars
    for (int i = tid; i < SPB * TC; i += NTHR)
        ch[i] = chars[blockIdx.x * SPB * TC + i];

    __syncthreads();   // publish ch + h buffer 0 BEFORE any thread reads them

    const uint32_t h_base = smem_u32(&h_sm[0][0]);
    const int unit0 = 8 * w + 2 * cpair;        // units: unit0 + e (e=0,1)

    float c_reg[4];                              // [hh*2 + e]
#pragma unroll
    for (int j = 0; j < 4; j++) c_reg[j] = 0.0f;

    // ---- D init: EWb rows for step 0 ----
    float d[16];                                 // d[g*4 + hh*2 + e]
    {
        int v0 = ch[r * TC], v1 = ch[(r + 8) * TC];
#pragma unroll
        for (int g = 0; g < 4; g++) {
            float2 t0 = __ldg((const float2*)(g_EWb + v0 * G4 + g * 64 + unit0));
            float2 t1 = __ldg((const float2*)(g_EWb + v1 * G4 + g * 64 + unit0));
            d[g * 4 + 0] = t0.x; d[g * 4 + 1] = t0.y;
            d[g * 4 + 2] = t1.x; d[g * 4 + 3] = t1.y;
        }
    }

#pragma unroll 1
    for (int step = 0; step < TC; step++) {
        const int rb = step & 1;

        // ---- GEMM: D += A(h) * B(U-in-regs), 32 HMMA / warp ----
        const uint32_t ha = h_base + (uint32_t)rb * 4096u + (uint32_t)lane * 16u;
#pragma unroll
        for (int kt = 0; kt < 8; kt++) {
            uint4 A; lds128u(A, ha + (uint32_t)kt * 512u);
#pragma unroll
            for (int g = 0; g < 4; g++)
                mma8(d[g * 4 + 0], d[g * 4 + 1], d[g * 4 + 2], d[g * 4 + 3],
                     A, breg[g][kt][0], breg[g][kt][1]);
        }

        // ---- gates (thread-local, 5 MUFU per (seq,unit)) ----
        float hv[4];
#pragma unroll
        for (int el = 0; el < 4; el++) {
            float zi = d[ 0 + el];
            float zf = d[ 4 + el];
            float zg = d[ 8 + el];
            float zo = d[12 + el];
            float ig = sigmoid_(zi), fg = sigmoid_(zf);
            float gg = tanha(zg),    og = sigmoid_(zo);
            float c  = fmaf(fg, c_reg[el], ig * gg);
            c_reg[el] = c;
            hv[el] = og * tanha(c);
        }

        if (step < TC - 1) {
            // ---- prefetch next step's EWb into D (L1-resident table) ----
            int v0 = ch[r * TC + step + 1], v1 = ch[(r + 8) * TC + step + 1];
#pragma unroll
            for (int g = 0; g < 4; g++) {
                float2 t0 = __ldg((const float2*)(g_EWb + v0 * G4 + g * 64 + unit0));
                float2 t1 = __ldg((const float2*)(g_EWb + v1 * G4 + g * 64 + unit0));
                d[g * 4 + 0] = t0.x; d[g * 4 + 1] = t0.y;
                d[g * 4 + 2] = t1.x; d[g * 4 + 3] = t1.y;
            }
            // ---- write h into A-frag layout of buffer rb^1 (warp owns kt=w) ----
            const uint32_t bw = h_base + (uint32_t)(rb ^ 1) * 4096u +
                                (uint32_t)w * 512u;
#pragma unroll
            for (int el = 0; el < 4; el++) {
                int e = el & 1, hh = el >> 1;
                int kcol = 2 * cpair + e;                     // unit % 8
                uint32_t addr = bw + (uint32_t)(r * 4 + (kcol & 3)) * 16u +
                                (uint32_t)((kcol >> 2) * 2 + hh) * 4u;
                sts32(addr, tf32_(hv[el]));
            }
            __syncthreads();
        } else {
            // ---- final h -> gmem ----
            const int gs = blockIdx.x * SPB + r;
#pragma unroll
            for (int hh = 0; hh < 2; hh++) {
                float2 v = make_float2(hv[hh * 2], hv[hh * 2 + 1]);
                *(float2*)(out + (size_t)(gs + hh * 8) * HU + unit0) = v;
            }
        }
    }
}

extern "C" void kernel_launch(void* const* d_in, const int* in_sizes, int n_in,
                              void* d_out, int out_size) {
    const int*   chars = (const int*)d_in[0];
    const float* E     = (const float*)d_in[1];
    const float* W     = (const float*)d_in[2];
    const float* U     = (const float*)d_in[3];
    const float* b     = (const float*)d_in[4];
    float* out = (float*)d_out;

    ewb_kernel<<<128, 256>>>(E, W, b);
    lstm_kernel<<<NBLK, NTHR>>>(chars, U, out);
}

// round 16
// speedup vs baseline: 3.2341x; 1.0803x over previous
#include <cuda_runtime.h>
#include <cstdint>

#define TC   25
#define HU   64
#define G4   256
#define SPB  16                  // sequences per CTA (one m16 tile)
#define NTHR 256
#define NSEQ 32768
#define NBLK (NSEQ / SPB)        // 2048 CTAs

// Gate-interleaved input-projection table:
// g_EWbG[v*256 + u*4 + g] = (E@W)[v][g*64+u] + b[g*64+u]
__device__ float g_EWbG[128 * G4];

__global__ void ewbg_kernel(const float* __restrict__ E,
                            const float* __restrict__ W,
                            const float* __restrict__ b) {
    int v = blockIdx.x, t = threadIdx.x;
    int u = t >> 2, g = t & 3;
    int col = g * 64 + u;
    float acc = b[col];
#pragma unroll
    for (int d = 0; d < 32; d++)
        acc = fmaf(E[v * 32 + d], W[d * G4 + col], acc);
    g_EWbG[v * G4 + t] = acc;
}

// ---------------- helpers ----------------
__device__ __forceinline__ uint32_t smem_u32(const void* p) {
    uint32_t a;
    asm("{ .reg .u64 t; cvta.to.shared.u64 t, %1; cvt.u32.u64 %0, t; }"
        : "=r"(a) : "l"(p));
    return a;
}
__device__ __forceinline__ float tanha(float x) {
    float y; asm("tanh.approx.f32 %0, %1;" : "=f"(y) : "f"(x)); return y;
}
__device__ __forceinline__ float sigmoid_(float x) {
    return fmaf(0.5f, tanha(0.5f * x), 0.5f);
}
__device__ __forceinline__ uint32_t tf32_(float x) {
    uint32_t u; asm("cvt.rna.tf32.f32 %0, %1;" : "=r"(u) : "f"(x)); return u;
}
__device__ __forceinline__ void lds128u(uint4& v, uint32_t a) {
    asm volatile("ld.shared.v4.b32 {%0,%1,%2,%3}, [%4];"
                 : "=r"(v.x), "=r"(v.y), "=r"(v.z), "=r"(v.w) : "r"(a));
}
__device__ __forceinline__ void sts32(uint32_t a, uint32_t v) {
    asm volatile("st.shared.b32 [%0], %1;" :: "r"(a), "r"(v) : "memory");
}
// m16n8k8 tf32 MMA, D==C in-place accumulate
__device__ __forceinline__ void mma8(float& d0, float& d1, float& d2, float& d3,
                                     const uint4& a, uint32_t b0, uint32_t b1) {
    asm volatile(
        "mma.sync.aligned.m16n8k8.row.col.f32.tf32.tf32.f32 "
        "{%0,%1,%2,%3}, {%4,%5,%6,%7}, {%8,%9}, {%0,%1,%2,%3};"
        : "+f"(d0), "+f"(d1), "+f"(d2), "+f"(d3)
        : "r"(a.x), "r"(a.y), "r"(a.z), "r"(a.w), "r"(b0), "r"(b1));
}

// ---------------------------------------------------------------------------
// smem: h double buffer in A-fragment layout [buf][kt(8)][lane(32)][slot(4)] f32
//       + chars [16][25]
__global__ void __launch_bounds__(NTHR, 2)
lstm_kernel(const int* __restrict__ chars,
            const float* __restrict__ U,
            float* __restrict__ out) {
    __shared__ __align__(16) float h_sm[2][8 * 32 * 4];   // 2 x 4 KB
    __shared__ int ch[SPB * TC];

    const int tid   = threadIdx.x;
    const int lane  = tid & 31;
    const int w     = tid >> 5;          // warp = unit group: units [8w, 8w+8)
    const int r     = lane >> 2;         // D rows r, r+8
    const int cpair = lane & 3;          // D col pair 2*cpair, 2*cpair+1
    const int klo   = lane & 3;          // B frag k-row low
    const int ncol  = lane >> 2;         // B frag n-col (unit offset 0..7)

    // ---- load B (= U, tf32) fragments into registers: constant all steps ----
    uint32_t breg[4][8][2];
#pragma unroll
    for (int g = 0; g < 4; g++)
#pragma unroll
        for (int kt = 0; kt < 8; kt++) {
            int col = g * 64 + 8 * w + ncol;
            breg[g][kt][0] = tf32_(__ldg(&U[(kt * 8 + klo)     * G4 + col]));
            breg[g][kt][1] = tf32_(__ldg(&U[(kt * 8 + klo + 4) * G4 + col]));
        }

    // zero h buffer 0 (h0 = 0)
    for (int i = tid; i < 8 * 32 * 4; i += NTHR) h_sm[0][i] = 0.0f;
    // stage chars
    for (int i = tid; i < SPB * TC; i += NTHR)
        ch[i] = chars[blockIdx.x * SPB * TC + i];

    __syncthreads();   // publish ch + h buffer 0 before any reads

    const uint32_t h_base = smem_u32(&h_sm[0][0]);
    const int unit0 = 8 * w + 2 * cpair;        // units: unit0 + e (e=0,1)

    float c_reg[4];                              // [hh*2 + e]
#pragma unroll
    for (int j = 0; j < 4; j++) c_reg[j] = 0.0f;

    // ---- D init: EWbG rows for step 0 (4 x LDG.128, quad-coalesced) ----
    float d[16];                                 // d[g*4 + hh*2 + e]
    {
        int v0 = ch[r * TC], v1 = ch[(r + 8) * TC];
#pragma unroll
        for (int hh = 0; hh < 2; hh++) {
            int v = hh ? v1 : v0;
#pragma unroll
            for (int e = 0; e < 2; e++) {
                float4 q = __ldg((const float4*)(g_EWbG + v * G4 + (unit0 + e) * 4));
                d[ 0 + hh * 2 + e] = q.x;
                d[ 4 + hh * 2 + e] = q.y;
                d[ 8 + hh * 2 + e] = q.z;
                d[12 + hh * 2 + e] = q.w;
            }
        }
    }

#pragma unroll 1
    for (int step = 0; step < TC; step++) {
        const int rb = step & 1;

        // ---- GEMM: D += A(h) * B(U-in-regs), 32 HMMA / warp ----
        const uint32_t ha = h_base + (uint32_t)rb * 4096u + (uint32_t)lane * 16u;
#pragma unroll
        for (int kt = 0; kt < 8; kt++) {
            uint4 A; lds128u(A, ha + (uint32_t)kt * 512u);
#pragma unroll
            for (int g = 0; g < 4; g++)
                mma8(d[g * 4 + 0], d[g * 4 + 1], d[g * 4 + 2], d[g * 4 + 3],
                     A, breg[g][kt][0], breg[g][kt][1]);
        }

        // ---- gates (thread-local, 5 MUFU per (seq,unit)) ----
        float hv[4];
#pragma unroll
        for (int el = 0; el < 4; el++) {
            float zi = d[ 0 + el];
            float zf = d[ 4 + el];
            float zg = d[ 8 + el];
            float zo = d[12 + el];
            float ig = sigmoid_(zi), fg = sigmoid_(zf);
            float gg = tanha(zg),    og = sigmoid_(zo);
            float c  = fmaf(fg, c_reg[el], ig * gg);
            c_reg[el] = c;
            hv[el] = og * tanha(c);
        }

        if (step < TC - 1) {
            // ---- write h into A-frag layout of buffer rb^1 FIRST (barrier dep) ----
            const uint32_t bw = h_base + (uint32_t)(rb ^ 1) * 4096u +
                                (uint32_t)w * 512u;
#pragma unroll
            for (int el = 0; el < 4; el++) {
                int e = el & 1, hh = el >> 1;
                int kcol = 2 * cpair + e;                     // unit % 8
                uint32_t addr = bw + (uint32_t)(r * 4 + (kcol & 3)) * 16u +
                                (uint32_t)((kcol >> 2) * 2 + hh) * 4u;
                sts32(addr, tf32_(hv[el]));
            }
            // ---- prefetch next step's EWbG into D (overlaps barrier wait) ----
            int v0 = ch[r * TC + step + 1], v1 = ch[(r + 8) * TC + step + 1];
#pragma unroll
            for (int hh = 0; hh < 2; hh++) {
                int v = hh ? v1 : v0;
#pragma unroll
                for (int e = 0; e < 2; e++) {
                    float4 q = __ldg((const float4*)(g_EWbG + v * G4 + (unit0 + e) * 4));
                    d[ 0 + hh * 2 + e] = q.x;
                    d[ 4 + hh * 2 + e] = q.y;
                    d[ 8 + hh * 2 + e] = q.z;
                    d[12 + hh * 2 + e] = q.w;
                }
            }
            __syncthreads();
        } else {
            // ---- final h -> gmem ----
            const int gs = blockIdx.x * SPB + r;
#pragma unroll
            for (int hh = 0; hh < 2; hh++) {
                float2 v = make_float2(hv[hh * 2], hv[hh * 2 + 1]);
                *(float2*)(out + (size_t)(gs + hh * 8) * HU + unit0) = v;
            }
        }
    }
}

extern "C" void kernel_launch(void* const* d_in, const int* in_sizes, int n_in,
                              void* d_out, int out_size) {
    const int*   chars = (const int*)d_in[0];
    const float* E     = (const float*)d_in[1];
    const float* W     = (const float*)d_in[2];
    const float* U     = (const float*)d_in[3];
    const float* b     = (const float*)d_in[4];
    float* out = (float*)d_out;

    ewbg_kernel<<<128, 256>>>(E, W, b);
    lstm_kernel<<<NBLK, NTHR>>>(chars, U, out);
}

// round 17
// speedup vs baseline: 5.5651x; 1.7207x over previous
#include <cuda_runtime.h>
#include <cuda_fp16.h>
#include <cstdint>

#define TC   25
#define HU   64
#define G4   256
#define SPB  16                  // sequences per CTA (one m16 tile)
#define NTHR 256
#define NSEQ 32768
#define NBLK (NSEQ / SPB)        // 2048 CTAs

// Gate-interleaved fp16 input-projection table:
// g_EWbH[v*256 + u*4 + g] = fp16( (E@W)[v][g*64+u] + b[g*64+u] )
__device__ __half g_EWbH[128 * G4];

__global__ void ewbh_kernel(const float* __restrict__ E,
                            const float* __restrict__ W,
                            const float* __restrict__ b) {
    int v = blockIdx.x, t = threadIdx.x;
    int u = t >> 2, g = t & 3;
    int col = g * 64 + u;
    float acc = b[col];
#pragma unroll
    for (int d = 0; d < 32; d++)
        acc = fmaf(E[v * 32 + d], W[d * G4 + col], acc);
    g_EWbH[v * G4 + t] = __float2half_rn(acc);
}

// ---------------- helpers ----------------
__device__ __forceinline__ uint32_t smem_u32(const void* p) {
    uint32_t a;
    asm("{ .reg .u64 t; cvta.to.shared.u64 t, %1; cvt.u32.u64 %0, t; }"
        : "=r"(a) : "l"(p));
    return a;
}
__device__ __forceinline__ float tanha(float x) {
    float y; asm("tanh.approx.f32 %0, %1;" : "=f"(y) : "f"(x)); return y;
}
__device__ __forceinline__ float sigmoid_(float x) {
    return fmaf(0.5f, tanha(0.5f * x), 0.5f);
}
__device__ __forceinline__ void lds128u(uint4& v, uint32_t a) {
    asm volatile("ld.shared.v4.b32 {%0,%1,%2,%3}, [%4];"
                 : "=r"(v.x), "=r"(v.y), "=r"(v.z), "=r"(v.w) : "r"(a));
}
__device__ __forceinline__ void sts64u(uint32_t a, uint32_t v0, uint32_t v1) {
    asm volatile("st.shared.v2.b32 [%0], {%1,%2};"
                 :: "r"(a), "r"(v0), "r"(v1) : "memory");
}
__device__ __forceinline__ uint32_t packh2(float lo, float hi) {
    __half2 h = __floats2half2_rn(lo, hi);
    return *(uint32_t*)&h;
}
// m16n8k16 fp16 MMA, fp32 accumulate in place
__device__ __forceinline__ void mma16(float& d0, float& d1, float& d2, float& d3,
                                      const uint4& a, uint32_t b0, uint32_t b1) {
    asm volatile(
        "mma.sync.aligned.m16n8k16.row.col.f32.f16.f16.f32 "
        "{%0,%1,%2,%3}, {%4,%5,%6,%7}, {%8,%9}, {%0,%1,%2,%3};"
        : "+f"(d0), "+f"(d1), "+f"(d2), "+f"(d3)
        : "r"(a.x), "r"(a.y), "r"(a.z), "r"(a.w), "r"(b0), "r"(b1));
}

// ---------------------------------------------------------------------------
// smem: h double buffer in fp16 A-fragment layout
//       [buf][kt(4)][lane(32)][slot(4) b32]  -> 2 KB per buffer
__global__ void __launch_bounds__(NTHR, 2)
lstm_kernel(const int* __restrict__ chars,
            const float* __restrict__ U,
            float* __restrict__ out) {
    __shared__ __align__(16) uint32_t h_sm[2][4 * 32 * 4];   // 2 x 2 KB
    __shared__ int ch[SPB * TC];

    const int tid   = threadIdx.x;
    const int lane  = tid & 31;
    const int w     = tid >> 5;          // warp = unit group: units [8w, 8w+8)
    const int r     = lane >> 2;         // D rows r, r+8
    const int cpair = lane & 3;          // D col pair 2*cpair, 2*cpair+1
    const int klo   = lane & 3;          // B frag k-row pair index
    const int ncol  = lane >> 2;         // B frag n-col (unit offset 0..7)

    // ---- B (= U, fp16) fragments in registers: constant across all steps ----
    // breg[g][kt][0] = {U[kt*16+2klo][col], U[kt*16+2klo+1][col]}
    // breg[g][kt][1] = {U[kt*16+2klo+8][col], U[kt*16+2klo+9][col]}
    uint32_t breg[4][4][2];
#pragma unroll
    for (int g = 0; g < 4; g++)
#pragma unroll
        for (int kt = 0; kt < 4; kt++) {
            int col = g * 64 + 8 * w + ncol;
            int k0  = kt * 16 + 2 * klo;
            breg[g][kt][0] = packh2(__ldg(&U[(k0    ) * G4 + col]),
                                    __ldg(&U[(k0 + 1) * G4 + col]));
            breg[g][kt][1] = packh2(__ldg(&U[(k0 + 8) * G4 + col]),
                                    __ldg(&U[(k0 + 9) * G4 + col]));
        }

    // zero h buffer 0 (h0 = 0; fp16 zero = 0x0000)
    for (int i = tid; i < 4 * 32 * 4; i += NTHR) h_sm[0][i] = 0u;
    // stage chars
    for (int i = tid; i < SPB * TC; i += NTHR)
        ch[i] = chars[blockIdx.x * SPB * TC + i];

    __syncthreads();   // publish ch + h buffer 0 before any reads

    const uint32_t h_base = smem_u32(&h_sm[0][0]);
    const int unit0 = 8 * w + 2 * cpair;        // even; units unit0, unit0+1
    const int wkt   = w >> 1;                    // A k-tile this warp's units live in
    const int wkh   = w & 1;                     // k-high half within that tile

    float c_reg[4];                              // [hh*2 + e]
#pragma unroll
    for (int j = 0; j < 4; j++) c_reg[j] = 0.0f;

    // ---- D init: EWbH rows for step 0 (2 x LDG.128, 16 fp16 each thread) ----
    float d[16];                                 // d[g*4 + hh*2 + e]
    {
        int vv[2] = { ch[r * TC], ch[(r + 8) * TC] };
#pragma unroll
        for (int hh = 0; hh < 2; hh++) {
            uint4 q = __ldg((const uint4*)(g_EWbH + vv[hh] * G4 + unit0 * 4));
            float2 x = __half22float2(*(__half2*)&q.x);   // u0: g0,g1
            float2 y = __half22float2(*(__half2*)&q.y);   // u0: g2,g3
            float2 z = __half22float2(*(__half2*)&q.z);   // u1: g0,g1
            float2 t = __half22float2(*(__half2*)&q.w);   // u1: g2,g3
            d[ 0 + hh * 2 + 0] = x.x; d[ 4 + hh * 2 + 0] = x.y;
            d[ 8 + hh * 2 + 0] = y.x; d[12 + hh * 2 + 0] = y.y;
            d[ 0 + hh * 2 + 1] = z.x; d[ 4 + hh * 2 + 1] = z.y;
            d[ 8 + hh * 2 + 1] = t.x; d[12 + hh * 2 + 1] = t.y;
        }
    }

#pragma unroll 1
    for (int step = 0; step < TC; step++) {
        const int rb = step & 1;

        // ---- GEMM: D += A(h,fp16) * B(U-in-regs), 16 HMMA / warp ----
        const uint32_t ha = h_base + (uint32_t)rb * 2048u + (uint32_t)lane * 16u;
#pragma unroll
        for (int kt = 0; kt < 4; kt++) {
            uint4 A; lds128u(A, ha + (uint32_t)kt * 512u);
#pragma unroll
            for (int g = 0; g < 4; g++)
                mma16(d[g * 4 + 0], d[g * 4 + 1], d[g * 4 + 2], d[g * 4 + 3],
                      A, breg[g][kt][0], breg[g][kt][1]);
        }

        // ---- gates (thread-local, 5 MUFU per (seq,unit)) ----
        float hv[4];
#pragma unroll
        for (int el = 0; el < 4; el++) {
            float zi = d[ 0 + el];
            float zf = d[ 4 + el];
            float zg = d[ 8 + el];
            float zo = d[12 + el];
            float ig = sigmoid_(zi), fg = sigmoid_(zf);
            float gg = tanha(zg),    og = sigmoid_(zo);
            float c  = fmaf(fg, c_reg[el], ig * gg);
            c_reg[el] = c;
            hv[el] = og * tanha(c);
        }

        if (step < TC - 1) {
            // ---- write h (fp16x2) into A-frag layout of buffer rb^1 ----
            // seq r   -> slot 2*wkh,   seq r+8 -> slot 2*wkh+1  (adjacent: STS.64)
            const uint32_t addr = h_base + (uint32_t)(rb ^ 1) * 2048u +
                                  (uint32_t)wkt * 512u +
                                  (uint32_t)(r * 4 + cpair) * 16u +
                                  (uint32_t)wkh * 8u;
            sts64u(addr, packh2(hv[0], hv[1]), packh2(hv[2], hv[3]));

            // ---- prefetch next step's EWbH into D (overlaps barrier wait) ----
            int vv[2] = { ch[r * TC + step + 1], ch[(r + 8) * TC + step + 1] };
#pragma unroll
            for (int hh = 0; hh < 2; hh++) {
                uint4 q = __ldg((const uint4*)(g_EWbH + vv[hh] * G4 + unit0 * 4));
                float2 x = __half22float2(*(__half2*)&q.x);
                float2 y = __half22float2(*(__half2*)&q.y);
                float2 z = __half22float2(*(__half2*)&q.z);
                float2 t = __half22float2(*(__half2*)&q.w);
                d[ 0 + hh * 2 + 0] = x.x; d[ 4 + hh * 2 + 0] = x.y;
                d[ 8 + hh * 2 + 0] = y.x; d[12 + hh * 2 + 0] = y.y;
                d[ 0 + hh * 2 + 1] = z.x; d[ 4 + hh * 2 + 1] = z.y;
                d[ 8 + hh * 2 + 1] = t.x; d[12 + hh * 2 + 1] = t.y;
            }
            __syncthreads();
        } else {
            // ---- final h -> gmem (fp32, never quantized) ----
            const int gs = blockIdx.x * SPB + r;
#pragma unroll
            for (int hh = 0; hh < 2; hh++) {
                float2 v = make_float2(hv[hh * 2], hv[hh * 2 + 1]);
                *(float2*)(out + (size_t)(gs + hh * 8) * HU + unit0) = v;
            }
        }
    }
}

extern "C" void kernel_launch(void* const* d_in, const int* in_sizes, int n_in,
                              void* d_out, int out_size) {
    const int*   chars = (const int*)d_in[0];
    const float* E     = (const float*)d_in[1];
    const float* W     = (const float*)d_in[2];
    const float* U     = (const float*)d_in[3];
    const float* b     = (const float*)d_in[4];
    float* out = (float*)d_out;

    ewbh_kernel<<<128, 256>>>(E, W, b);
    lstm_kernel<<<NBLK, NTHR>>>(chars, U, out);
}